// round 15
// baseline (speedup 1.0000x reference)
#include <cuda_runtime.h>
#include <cuda_bf16.h>
#include <math.h>
#include <stdint.h>

// Problem constants
#define BSZ 4096
#define NN  8192          // N = 2*B
#define DD  512
#define INV_T 2.0f        // 1 / temperature

// GEMM tiling
#define BM 128
#define BN 128
#define BK 64             // 128B rows -> SW128 swizzle
#define NT 64             // NN / 128 column blocks
#define NTILES 2080       // 64*65/2 upper-triangular tiles

#define FULLMASK 0xFFFFFFFFu
#define NEGINF (-INFINITY)

// Dynamic smem: A0 | A1 | B0 | B1, each 128x64 bf16 = 16KB. Total 64KB.
#define TILE_ELEMS (BM * BK)
#define SMEM_BYTES (4 * TILE_ELEMS * 2)

// Scratch (static device allocations only)
__device__ __nv_bfloat16 g_hb[(size_t)NN * DD];     // 8 MB
__device__ float2 g_part[(size_t)NN * NT];          // 4 MB (max,sumexp)
__device__ float g_pos[NN];
__device__ float g_rowval[NN];
__device__ unsigned int g_bar_arrive;               // grid barrier: arrivals
__device__ unsigned int g_bar_gen;                  // grid barrier: generation

// ---------------------------------------------------------------------------
// helpers
// ---------------------------------------------------------------------------
__device__ __forceinline__ uint32_t smem_u32(const void* p) {
    uint32_t a;
    asm("{ .reg .u64 t; cvta.to.shared.u64 t, %1; cvt.u32.u64 %0, t; }"
        : "=r"(a) : "l"(p));
    return a;
}

__device__ __forceinline__ void mma_bf16(float c[4], const uint32_t a[4],
                                         uint32_t b0, uint32_t b1) {
    asm volatile(
        "mma.sync.aligned.m16n8k16.row.col.f32.bf16.bf16.f32 "
        "{%0,%1,%2,%3}, {%4,%5,%6,%7}, {%8,%9}, {%0,%1,%2,%3};\n"
        : "+f"(c[0]), "+f"(c[1]), "+f"(c[2]), "+f"(c[3])
        : "r"(a[0]), "r"(a[1]), "r"(a[2]), "r"(a[3]), "r"(b0), "r"(b1));
}

__device__ __forceinline__ void ldsm_x4(uint32_t r[4], uint32_t addr) {
    asm volatile(
        "ldmatrix.sync.aligned.m8n8.x4.shared.b16 {%0,%1,%2,%3}, [%4];"
        : "=r"(r[0]), "=r"(r[1]), "=r"(r[2]), "=r"(r[3]) : "r"(addr));
}

__device__ __forceinline__ void cp_async16(uint32_t smem_dst, const void* g) {
    asm volatile("cp.async.cg.shared.global [%0], [%1], 16;\n"
                 :: "r"(smem_dst), "l"(g));
}

__device__ __forceinline__ float2 lse_combine(float2 a, float2 b) {
    float m = fmaxf(a.x, b.x);
    float s = a.y * __expf(a.x - m) + b.y * __expf(b.x - m);
    return make_float2(m, s);
}

__device__ __forceinline__ uint32_t sw128(uint32_t off) {
    return off ^ ((off >> 3) & 0x70);
}

// Grid barrier: all CTAs resident (grid == one wave). Generation counter is
// monotonic -> reusable any number of times, and across graph replays.
__device__ __forceinline__ void grid_barrier(int tid) {
    __syncthreads();
    if (tid == 0) {
        __threadfence();
        unsigned int gen =
            *reinterpret_cast<volatile unsigned int*>(&g_bar_gen);
        unsigned int a = atomicAdd(&g_bar_arrive, 1u);
        if (a == gridDim.x - 1) {
            g_bar_arrive = 0;
            __threadfence();
            atomicAdd(&g_bar_gen, 1u);     // release
        } else {
            while (*reinterpret_cast<volatile unsigned int*>(&g_bar_gen)
                   == gen) { }
            __threadfence();
        }
    }
    __syncthreads();
}

// ---------------------------------------------------------------------------
// Single persistent kernel:
//   phase 0: fp32->bf16 convert           (grid-stride)
//   phase 1: fused triangular GEMM + masked LSE partials
//   phase 2: per-row combine of 64 partials -> g_rowval
//   phase 3: block 0 deterministic final sum -> out[0]
// ---------------------------------------------------------------------------
__global__ __launch_bounds__(256) void gemm_fused_kernel(
    const float4* __restrict__ hi, const float4* __restrict__ hj,
    float* __restrict__ out) {
    extern __shared__ __nv_bfloat16 dsm[];
    __shared__ float2 rowRed[128][4];
    __shared__ float2 colRed[128][2];

    const uint32_t smemBase = smem_u32(dsm);

    const int tid  = threadIdx.x;
    const int warp = tid >> 5;
    const int lane = tid & 31;
    const int warpM = warp >> 2;
    const int warpN = warp & 3;
    const int grp = lane >> 2;
    const int tg  = lane & 3;
    const int lrow = lane & 15;
    const int lhi  = (lane >> 4) * 16;

    // ---- Phase 0: convert h_i, h_j -> bf16 (grid-stride) ----
    {
        __nv_bfloat162* da = reinterpret_cast<__nv_bfloat162*>(g_hb);
        __nv_bfloat162* db =
            reinterpret_cast<__nv_bfloat162*>(g_hb + (size_t)BSZ * DD);
        const int total = BSZ * DD / 4;
        for (int idx = blockIdx.x * 256 + tid; idx < total;
             idx += gridDim.x * 256) {
            float4 a = hi[idx];
            float4 b = hj[idx];
            da[idx * 2]     = __floats2bfloat162_rn(a.x, a.y);
            da[idx * 2 + 1] = __floats2bfloat162_rn(a.z, a.w);
            db[idx * 2]     = __floats2bfloat162_rn(b.x, b.y);
            db[idx * 2 + 1] = __floats2bfloat162_rn(b.z, b.w);
        }
    }

    grid_barrier(tid);

    // ---- Phase 1: persistent tile loop (static stride) ----
    for (int tile = blockIdx.x; tile < NTILES; tile += gridDim.x) {
        // Decode upper-triangular tile index
        int tm = (int)((129.0f - sqrtf(129.0f * 129.0f - 8.0f * (float)tile)) * 0.5f);
        while (tm > 0 && tm * (129 - tm) / 2 > tile) tm--;
        while ((tm + 1) * (129 - (tm + 1)) / 2 <= tile) tm++;
        const int tn = tm + (tile - tm * (129 - tm) / 2);

        const int rowBase = tm * BM;
        const int colBase = tn * BN;
        const bool diagTile = (tm == tn);
        const bool posTile  = (colBase - rowBase == BSZ);

        float acc[4][4][4];
        #pragma unroll
        for (int mi = 0; mi < 4; mi++)
            #pragma unroll
            for (int ni = 0; ni < 4; ni++)
                #pragma unroll
                for (int r = 0; r < 4; r++) acc[mi][ni][r] = 0.0f;

        auto load_chunk = [&](int kb, int buf) {
            const int kg = kb * BK;
            const uint32_t aB = smemBase + buf * (TILE_ELEMS * 2);
            const uint32_t bB = smemBase + (2 + buf) * (TILE_ELEMS * 2);
            #pragma unroll
            for (int j = 0; j < 4; j++) {
                int lin = tid + j * 256;
                int r = lin >> 3, c16 = lin & 7;
                uint32_t sw = sw128(r * 128 + c16 * 16);
                cp_async16(aB + sw, g_hb + (size_t)(rowBase + r) * DD + kg + c16 * 8);
                cp_async16(bB + sw, g_hb + (size_t)(colBase + r) * DD + kg + c16 * 8);
            }
            asm volatile("cp.async.commit_group;\n" ::: "memory");
        };

        load_chunk(0, 0);

        #pragma unroll 1
        for (int kb = 0; kb < DD / BK; kb++) {
            const int buf = kb & 1;
            if (kb + 1 < DD / BK) {
                load_chunk(kb + 1, (kb + 1) & 1);
                asm volatile("cp.async.wait_group 1;\n" ::: "memory");
            } else {
                asm volatile("cp.async.wait_group 0;\n" ::: "memory");
            }
            __syncthreads();

            const uint32_t aB = smemBase + buf * (TILE_ELEMS * 2);
            const uint32_t bB = smemBase + (2 + buf) * (TILE_ELEMS * 2);

            #pragma unroll
            for (int ks = 0; ks < 4; ks++) {
                const int cb = lhi + ks * 32;

                uint32_t af[4][4];
                #pragma unroll
                for (int mi = 0; mi < 4; mi++) {
                    uint32_t off = (warpM * 64 + mi * 16 + lrow) * 128 + cb;
                    ldsm_x4(af[mi], aB + sw128(off));
                }
                uint32_t bq[2][4];
                #pragma unroll
                for (int n2 = 0; n2 < 2; n2++) {
                    uint32_t off = (warpN * 32 + n2 * 16 + lrow) * 128 + cb;
                    ldsm_x4(bq[n2], bB + sw128(off));
                }
                #pragma unroll
                for (int mi = 0; mi < 4; mi++)
                    #pragma unroll
                    for (int ni = 0; ni < 4; ni++)
                        mma_bf16(acc[mi][ni], af[mi],
                                 bq[ni >> 1][ni & 1], bq[ni >> 1][(ni & 1) + 2]);
            }
            __syncthreads();
        }

        // ---- Epilogue: scale, mask diagonal, extract positive pairs ----
        #pragma unroll
        for (int mi = 0; mi < 4; mi++) {
            const int gr_a = rowBase + warpM * 64 + mi * 16 + grp;
            const int gr_b = gr_a + 8;
            #pragma unroll
            for (int ni = 0; ni < 4; ni++) {
                const int gc0 = colBase + warpN * 32 + ni * 8 + tg * 2;
                const int gc1 = gc0 + 1;
                float v0 = acc[mi][ni][0] * INV_T;
                float v1 = acc[mi][ni][1] * INV_T;
                float v2 = acc[mi][ni][2] * INV_T;
                float v3 = acc[mi][ni][3] * INV_T;
                if (posTile) {
                    if (gc0 == gr_a + BSZ) { g_pos[gr_a] = v0; g_pos[gc0] = v0; }
                    if (gc1 == gr_a + BSZ) { g_pos[gr_a] = v1; g_pos[gc1] = v1; }
                    if (gc0 == gr_b + BSZ) { g_pos[gr_b] = v2; g_pos[gc0] = v2; }
                    if (gc1 == gr_b + BSZ) { g_pos[gr_b] = v3; g_pos[gc1] = v3; }
                }
                if (diagTile) {
                    if (gr_a == gc0) v0 = NEGINF;
                    if (gr_a == gc1) v1 = NEGINF;
                    if (gr_b == gc0) v2 = NEGINF;
                    if (gr_b == gc1) v3 = NEGINF;
                }
                acc[mi][ni][0] = v0; acc[mi][ni][1] = v1;
                acc[mi][ni][2] = v2; acc[mi][ni][3] = v3;
            }
        }

        // ---- Row-side reduction (per-row max) ----
        #pragma unroll
        for (int mi = 0; mi < 4; mi++) {
            float mA = NEGINF, mB = NEGINF;
            #pragma unroll
            for (int ni = 0; ni < 4; ni++) {
                mA = fmaxf(mA, fmaxf(acc[mi][ni][0], acc[mi][ni][1]));
                mB = fmaxf(mB, fmaxf(acc[mi][ni][2], acc[mi][ni][3]));
            }
            mA = fmaxf(mA, __shfl_xor_sync(FULLMASK, mA, 1));
            mA = fmaxf(mA, __shfl_xor_sync(FULLMASK, mA, 2));
            mB = fmaxf(mB, __shfl_xor_sync(FULLMASK, mB, 1));
            mB = fmaxf(mB, __shfl_xor_sync(FULLMASK, mB, 2));
            float sA = 0.0f, sB = 0.0f;
            #pragma unroll
            for (int ni = 0; ni < 4; ni++) {
                sA += __expf(acc[mi][ni][0] - mA) + __expf(acc[mi][ni][1] - mA);
                sB += __expf(acc[mi][ni][2] - mB) + __expf(acc[mi][ni][3] - mB);
            }
            sA += __shfl_xor_sync(FULLMASK, sA, 1);
            sA += __shfl_xor_sync(FULLMASK, sA, 2);
            sB += __shfl_xor_sync(FULLMASK, sB, 1);
            sB += __shfl_xor_sync(FULLMASK, sB, 2);
            if (tg == 0) {
                rowRed[warpM * 64 + mi * 16 + grp][warpN]     = make_float2(mA, sA);
                rowRed[warpM * 64 + mi * 16 + grp + 8][warpN] = make_float2(mB, sB);
            }
        }

        // ---- Col-side reduction (symmetry; per-col max) ----
        if (!diagTile) {
            #pragma unroll
            for (int ni = 0; ni < 4; ni++) {
                float m0 = NEGINF, m1 = NEGINF;
                #pragma unroll
                for (int mi = 0; mi < 4; mi++) {
                    m0 = fmaxf(m0, fmaxf(acc[mi][ni][0], acc[mi][ni][2]));
                    m1 = fmaxf(m1, fmaxf(acc[mi][ni][1], acc[mi][ni][3]));
                }
                #pragma unroll
                for (int d = 4; d < 32; d <<= 1) {
                    m0 = fmaxf(m0, __shfl_xor_sync(FULLMASK, m0, d));
                    m1 = fmaxf(m1, __shfl_xor_sync(FULLMASK, m1, d));
                }
                float s0 = 0.0f, s1 = 0.0f;
                #pragma unroll
                for (int mi = 0; mi < 4; mi++) {
                    s0 += __expf(acc[mi][ni][0] - m0) + __expf(acc[mi][ni][2] - m0);
                    s1 += __expf(acc[mi][ni][1] - m1) + __expf(acc[mi][ni][3] - m1);
                }
                #pragma unroll
                for (int d = 4; d < 32; d <<= 1) {
                    s0 += __shfl_xor_sync(FULLMASK, s0, d);
                    s1 += __shfl_xor_sync(FULLMASK, s1, d);
                }
                if (grp == 0) {
                    colRed[warpN * 32 + ni * 8 + tg * 2][warpM]     = make_float2(m0, s0);
                    colRed[warpN * 32 + ni * 8 + tg * 2 + 1][warpM] = make_float2(m1, s1);
                }
            }
        }
        __syncthreads();

        // ---- Store partials ----
        if (tid < 128) {
            float2 p = rowRed[tid][0];
            p = lse_combine(p, rowRed[tid][1]);
            p = lse_combine(p, rowRed[tid][2]);
            p = lse_combine(p, rowRed[tid][3]);
            g_part[(size_t)(rowBase + tid) * NT + tn] = p;
        } else if (!diagTile) {
            int c = tid - 128;
            float2 p = lse_combine(colRed[c][0], colRed[c][1]);
            g_part[(size_t)(colBase + c) * NT + tm] = p;
        }
        // next iteration's mainloop __syncthreads orders rowRed/colRed reuse
    }

    grid_barrier(tid);

    // ---- Phase 2: per-row combine of 64 partials (one warp per row) ----
    {
        const int gwarp  = blockIdx.x * 8 + warp;
        const int nwarps = gridDim.x * 8;
        for (int row = gwarp; row < NN; row += nwarps) {
            float2 p = g_part[(size_t)row * NT + lane * 2];
            float2 q = g_part[(size_t)row * NT + lane * 2 + 1];
            p = lse_combine(p, q);
            float m = p.x, s = p.y;
            #pragma unroll
            for (int d = 1; d < 32; d <<= 1) {
                float mo = __shfl_xor_sync(FULLMASK, m, d);
                float so = __shfl_xor_sync(FULLMASK, s, d);
                float mm = fmaxf(m, mo);
                s = s * __expf(m - mm) + so * __expf(mo - mm);
                m = mm;
            }
            if (lane == 0) g_rowval[row] = m + logf(s) - g_pos[row];
        }
    }

    grid_barrier(tid);

    // ---- Phase 3: block 0 deterministic final sum ----
    if (blockIdx.x == 0) {
        float sum = 0.0f;
        #pragma unroll
        for (int k = 0; k < 32; k++) sum += g_rowval[k * 256 + tid];
        __shared__ float sm[256];
        sm[tid] = sum;
        __syncthreads();
        #pragma unroll
        for (int st = 128; st > 0; st >>= 1) {
            if (tid < st) sm[tid] += sm[tid + st];
            __syncthreads();
        }
        if (tid == 0) out[0] = sm[0] / (float)NN;
    }
}

// ---------------------------------------------------------------------------
extern "C" void kernel_launch(void* const* d_in, const int* in_sizes, int n_in,
                              void* d_out, int out_size) {
    const float* hi = (const float*)d_in[0];
    const float* hj = (const float*)d_in[1];
    float* out = (float*)d_out;

    cudaFuncSetAttribute(gemm_fused_kernel,
                         cudaFuncAttributeMaxDynamicSharedMemorySize, SMEM_BYTES);

    int dev = 0, nsm = 148, occ = 2;
    cudaGetDevice(&dev);
    cudaDeviceGetAttribute(&nsm, cudaDevAttrMultiProcessorCount, dev);
    cudaOccupancyMaxActiveBlocksPerMultiprocessor(
        &occ, gemm_fused_kernel, 256, SMEM_BYTES);
    if (occ < 1) occ = 1;
    int grid = nsm * occ;                 // exactly one resident wave
    if (grid > NTILES) grid = NTILES;

    gemm_fused_kernel<<<grid, 256, SMEM_BYTES>>>(
        (const float4*)hi, (const float4*)hj, out);
}

// round 16
// speedup vs baseline: 1.0650x; 1.0650x over previous
#include <cuda_runtime.h>
#include <cuda_bf16.h>
#include <math.h>
#include <stdint.h>

// Problem constants
#define BSZ 4096
#define NN  8192          // N = 2*B
#define DD  512
#define INV_T 2.0f        // 1 / temperature

// GEMM tiling
#define BM 128
#define BN 128
#define BK 64             // 128B rows -> SW128 swizzle
#define NT 64             // NN / 128 column blocks
#define NTILES 2080       // 64*65/2 upper-triangular tiles

#define FULLMASK 0xFFFFFFFFu
#define NEGINF (-INFINITY)

// Dynamic smem: 3 stages x (A 16KB + B 16KB) = 96KB
#define STAGE_BYTES 32768
#define SMEM_BYTES (3 * STAGE_BYTES)

// Scratch (static device allocations only)
__device__ __nv_bfloat16 g_hb[(size_t)NN * DD];     // 8 MB
__device__ float2 g_part[(size_t)NN * NT];          // 4 MB (max,sumexp)
__device__ float g_pos[NN];
__device__ float g_rowval[NN];
__device__ int g_done;                              // zero-init
__device__ unsigned int g_bar_arrive;               // grid barrier: arrivals
__device__ unsigned int g_bar_gen;                  // grid barrier: generation

// ---------------------------------------------------------------------------
// helpers
// ---------------------------------------------------------------------------
__device__ __forceinline__ uint32_t smem_u32(const void* p) {
    uint32_t a;
    asm("{ .reg .u64 t; cvta.to.shared.u64 t, %1; cvt.u32.u64 %0, t; }"
        : "=r"(a) : "l"(p));
    return a;
}

__device__ __forceinline__ void mma_bf16(float c[4], const uint32_t a[4],
                                         uint32_t b0, uint32_t b1) {
    asm volatile(
        "mma.sync.aligned.m16n8k16.row.col.f32.bf16.bf16.f32 "
        "{%0,%1,%2,%3}, {%4,%5,%6,%7}, {%8,%9}, {%0,%1,%2,%3};\n"
        : "+f"(c[0]), "+f"(c[1]), "+f"(c[2]), "+f"(c[3])
        : "r"(a[0]), "r"(a[1]), "r"(a[2]), "r"(a[3]), "r"(b0), "r"(b1));
}

__device__ __forceinline__ void ldsm_x4(uint32_t r[4], uint32_t addr) {
    asm volatile(
        "ldmatrix.sync.aligned.m8n8.x4.shared.b16 {%0,%1,%2,%3}, [%4];"
        : "=r"(r[0]), "=r"(r[1]), "=r"(r[2]), "=r"(r[3]) : "r"(addr));
}

__device__ __forceinline__ void cp_async16(uint32_t smem_dst, const void* g) {
    asm volatile("cp.async.cg.shared.global [%0], [%1], 16;\n"
                 :: "r"(smem_dst), "l"(g));
}

__device__ __forceinline__ float2 lse_combine(float2 a, float2 b) {
    float m = fmaxf(a.x, b.x);
    float s = a.y * __expf(a.x - m) + b.y * __expf(b.x - m);
    return make_float2(m, s);
}

__device__ __forceinline__ uint32_t sw128(uint32_t off) {
    return off ^ ((off >> 3) & 0x70);
}

// Grid barrier: all CTAs resident (grid == one wave). Monotonic generation.
__device__ __forceinline__ void grid_barrier(int tid) {
    __syncthreads();
    if (tid == 0) {
        __threadfence();
        unsigned int gen =
            *reinterpret_cast<volatile unsigned int*>(&g_bar_gen);
        unsigned int a = atomicAdd(&g_bar_arrive, 1u);
        if (a == gridDim.x - 1) {
            g_bar_arrive = 0;
            __threadfence();
            atomicAdd(&g_bar_gen, 1u);     // release
        } else {
            while (*reinterpret_cast<volatile unsigned int*>(&g_bar_gen)
                   == gen) { }
            __threadfence();
        }
    }
    __syncthreads();
}

// ---------------------------------------------------------------------------
// Fused kernel: phase 0 convert -> grid barrier -> phase 1 persistent GEMM.
// Mainloop: 3-stage cp.async pipeline, ONE syncthreads per K-chunk,
// factored kernel-invariant ldmatrix addressing.
// ---------------------------------------------------------------------------
__global__ __launch_bounds__(256, 2) void gemm_fused_kernel(
    const float4* __restrict__ hi, const float4* __restrict__ hj) {
    extern __shared__ __nv_bfloat16 dsm[];
    __shared__ float2 rowRed[128][4];
    __shared__ float2 colRed[128][2];

    const uint32_t smemBase = smem_u32(dsm);

    const int tid  = threadIdx.x;
    const int warp = tid >> 5;
    const int lane = tid & 31;
    const int warpM = warp >> 2;
    const int warpN = warp & 3;
    const int grp = lane >> 2;
    const int tg  = lane & 3;
    const int lrow = lane & 15;
    const int lhi  = (lane >> 4) * 16;

    // ---- Phase 0: convert h_i, h_j -> bf16 (grid-stride) ----
    {
        __nv_bfloat162* da = reinterpret_cast<__nv_bfloat162*>(g_hb);
        __nv_bfloat162* db =
            reinterpret_cast<__nv_bfloat162*>(g_hb + (size_t)BSZ * DD);
        const int total = BSZ * DD / 4;
        for (int idx = blockIdx.x * 256 + tid; idx < total;
             idx += gridDim.x * 256) {
            float4 a = hi[idx];
            float4 b = hj[idx];
            da[idx * 2]     = __floats2bfloat162_rn(a.x, a.y);
            da[idx * 2 + 1] = __floats2bfloat162_rn(a.z, a.w);
            db[idx * 2]     = __floats2bfloat162_rn(b.x, b.y);
            db[idx * 2 + 1] = __floats2bfloat162_rn(b.z, b.w);
        }
    }

    grid_barrier(tid);

    // ---- Kernel-invariant ldmatrix address components ----
    // sw128(row*128 + cb) == row*128 + (cb ^ ((row&7)<<4)); row&7 == lrow&7
    // for ALL six fragment rows, so the swizzle factorizes per lane.
    const uint32_t swr = (uint32_t)(lrow & 7) << 4;
    uint32_t colOff[4];
    #pragma unroll
    for (int ks = 0; ks < 4; ks++)
        colOff[ks] = ((uint32_t)lhi ^ (swr & 0x10u)) |
                     (((uint32_t)ks * 32u) ^ (swr & 0x60u));
    uint32_t rowOffA[4], rowOffB[2];
    #pragma unroll
    for (int mi = 0; mi < 4; mi++)
        rowOffA[mi] = (uint32_t)(warpM * 64 + mi * 16 + lrow) * 128u;
    #pragma unroll
    for (int n2 = 0; n2 < 2; n2++)
        rowOffB[n2] = (uint32_t)(warpN * 32 + n2 * 16 + lrow) * 128u;

    // ---- Phase 1: persistent tile loop (static stride) ----
    for (int tile = blockIdx.x; tile < NTILES; tile += gridDim.x) {
        // Decode upper-triangular tile index
        int tm = (int)((129.0f - sqrtf(129.0f * 129.0f - 8.0f * (float)tile)) * 0.5f);
        while (tm > 0 && tm * (129 - tm) / 2 > tile) tm--;
        while ((tm + 1) * (129 - (tm + 1)) / 2 <= tile) tm++;
        const int tn = tm + (tile - tm * (129 - tm) / 2);

        const int rowBase = tm * BM;
        const int colBase = tn * BN;
        const bool diagTile = (tm == tn);
        const bool posTile  = (colBase - rowBase == BSZ);

        float acc[4][4][4];
        #pragma unroll
        for (int mi = 0; mi < 4; mi++)
            #pragma unroll
            for (int ni = 0; ni < 4; ni++)
                #pragma unroll
                for (int r = 0; r < 4; r++) acc[mi][ni][r] = 0.0f;

        auto load_chunk = [&](int kb, int st) {
            const int kg = kb * BK;
            const uint32_t aB = smemBase + st * STAGE_BYTES;
            const uint32_t bB = aB + 16384;
            #pragma unroll
            for (int j = 0; j < 4; j++) {
                int lin = tid + j * 256;
                int r = lin >> 3, c16 = lin & 7;
                uint32_t sw = sw128(r * 128 + c16 * 16);
                cp_async16(aB + sw, g_hb + (size_t)(rowBase + r) * DD + kg + c16 * 8);
                cp_async16(bB + sw, g_hb + (size_t)(colBase + r) * DD + kg + c16 * 8);
            }
            asm volatile("cp.async.commit_group;\n" ::: "memory");
        };

        load_chunk(0, 0);
        load_chunk(1, 1);

        #pragma unroll 1
        for (int kb = 0; kb < DD / BK; kb++) {
            if (kb < DD / BK - 1)
                asm volatile("cp.async.wait_group 1;\n" ::: "memory");
            else
                asm volatile("cp.async.wait_group 0;\n" ::: "memory");
            __syncthreads();   // single barrier per chunk

            if (kb + 2 < DD / BK) {
                int nst = kb + 2;
                load_chunk(nst, nst - (nst / 3) * 3);
            }

            const uint32_t aB = smemBase + (kb - (kb / 3) * 3) * STAGE_BYTES;
            const uint32_t bB = aB + 16384;

            #pragma unroll
            for (int ks = 0; ks < 4; ks++) {
                uint32_t af[4][4];
                #pragma unroll
                for (int mi = 0; mi < 4; mi++)
                    ldsm_x4(af[mi], aB + rowOffA[mi] + colOff[ks]);
                uint32_t bq[2][4];
                #pragma unroll
                for (int n2 = 0; n2 < 2; n2++)
                    ldsm_x4(bq[n2], bB + rowOffB[n2] + colOff[ks]);
                #pragma unroll
                for (int mi = 0; mi < 4; mi++)
                    #pragma unroll
                    for (int ni = 0; ni < 4; ni++)
                        mma_bf16(acc[mi][ni], af[mi],
                                 bq[ni >> 1][ni & 1], bq[ni >> 1][(ni & 1) + 2]);
            }
        }

        // ---- Epilogue: scale, mask diagonal, extract positive pairs ----
        #pragma unroll
        for (int mi = 0; mi < 4; mi++) {
            const int gr_a = rowBase + warpM * 64 + mi * 16 + grp;
            const int gr_b = gr_a + 8;
            #pragma unroll
            for (int ni = 0; ni < 4; ni++) {
                const int gc0 = colBase + warpN * 32 + ni * 8 + tg * 2;
                const int gc1 = gc0 + 1;
                float v0 = acc[mi][ni][0] * INV_T;
                float v1 = acc[mi][ni][1] * INV_T;
                float v2 = acc[mi][ni][2] * INV_T;
                float v3 = acc[mi][ni][3] * INV_T;
                if (posTile) {
                    if (gc0 == gr_a + BSZ) { g_pos[gr_a] = v0; g_pos[gc0] = v0; }
                    if (gc1 == gr_a + BSZ) { g_pos[gr_a] = v1; g_pos[gc1] = v1; }
                    if (gc0 == gr_b + BSZ) { g_pos[gr_b] = v2; g_pos[gc0] = v2; }
                    if (gc1 == gr_b + BSZ) { g_pos[gr_b] = v3; g_pos[gc1] = v3; }
                }
                if (diagTile) {
                    if (gr_a == gc0) v0 = NEGINF;
                    if (gr_a == gc1) v1 = NEGINF;
                    if (gr_b == gc0) v2 = NEGINF;
                    if (gr_b == gc1) v3 = NEGINF;
                }
                acc[mi][ni][0] = v0; acc[mi][ni][1] = v1;
                acc[mi][ni][2] = v2; acc[mi][ni][3] = v3;
            }
        }

        // ---- Row-side reduction (per-row max) ----
        #pragma unroll
        for (int mi = 0; mi < 4; mi++) {
            float mA = NEGINF, mB = NEGINF;
            #pragma unroll
            for (int ni = 0; ni < 4; ni++) {
                mA = fmaxf(mA, fmaxf(acc[mi][ni][0], acc[mi][ni][1]));
                mB = fmaxf(mB, fmaxf(acc[mi][ni][2], acc[mi][ni][3]));
            }
            mA = fmaxf(mA, __shfl_xor_sync(FULLMASK, mA, 1));
            mA = fmaxf(mA, __shfl_xor_sync(FULLMASK, mA, 2));
            mB = fmaxf(mB, __shfl_xor_sync(FULLMASK, mB, 1));
            mB = fmaxf(mB, __shfl_xor_sync(FULLMASK, mB, 2));
            float sA = 0.0f, sB = 0.0f;
            #pragma unroll
            for (int ni = 0; ni < 4; ni++) {
                sA += __expf(acc[mi][ni][0] - mA) + __expf(acc[mi][ni][1] - mA);
                sB += __expf(acc[mi][ni][2] - mB) + __expf(acc[mi][ni][3] - mB);
            }
            sA += __shfl_xor_sync(FULLMASK, sA, 1);
            sA += __shfl_xor_sync(FULLMASK, sA, 2);
            sB += __shfl_xor_sync(FULLMASK, sB, 1);
            sB += __shfl_xor_sync(FULLMASK, sB, 2);
            if (tg == 0) {
                rowRed[warpM * 64 + mi * 16 + grp][warpN]     = make_float2(mA, sA);
                rowRed[warpM * 64 + mi * 16 + grp + 8][warpN] = make_float2(mB, sB);
            }
        }

        // ---- Col-side reduction (symmetry; per-col max) ----
        if (!diagTile) {
            #pragma unroll
            for (int ni = 0; ni < 4; ni++) {
                float m0 = NEGINF, m1 = NEGINF;
                #pragma unroll
                for (int mi = 0; mi < 4; mi++) {
                    m0 = fmaxf(m0, fmaxf(acc[mi][ni][0], acc[mi][ni][2]));
                    m1 = fmaxf(m1, fmaxf(acc[mi][ni][1], acc[mi][ni][3]));
                }
                #pragma unroll
                for (int d = 4; d < 32; d <<= 1) {
                    m0 = fmaxf(m0, __shfl_xor_sync(FULLMASK, m0, d));
                    m1 = fmaxf(m1, __shfl_xor_sync(FULLMASK, m1, d));
                }
                float s0 = 0.0f, s1 = 0.0f;
                #pragma unroll
                for (int mi = 0; mi < 4; mi++) {
                    s0 += __expf(acc[mi][ni][0] - m0) + __expf(acc[mi][ni][2] - m0);
                    s1 += __expf(acc[mi][ni][1] - m1) + __expf(acc[mi][ni][3] - m1);
                }
                #pragma unroll
                for (int d = 4; d < 32; d <<= 1) {
                    s0 += __shfl_xor_sync(FULLMASK, s0, d);
                    s1 += __shfl_xor_sync(FULLMASK, s1, d);
                }
                if (grp == 0) {
                    colRed[warpN * 32 + ni * 8 + tg * 2][warpM]     = make_float2(m0, s0);
                    colRed[warpN * 32 + ni * 8 + tg * 2 + 1][warpM] = make_float2(m1, s1);
                }
            }
        }
        __syncthreads();   // orders stage reads (MMA) + rowRed/colRed writes

        // ---- Store partials ----
        if (tid < 128) {
            float2 p = rowRed[tid][0];
            p = lse_combine(p, rowRed[tid][1]);
            p = lse_combine(p, rowRed[tid][2]);
            p = lse_combine(p, rowRed[tid][3]);
            g_part[(size_t)(rowBase + tid) * NT + tn] = p;
        } else if (!diagTile) {
            int c = tid - 128;
            float2 p = lse_combine(colRed[c][0], colRed[c][1]);
            g_part[(size_t)(colBase + c) * NT + tm] = p;
        }
        // next tile's first in-loop __syncthreads orders smem reuse
    }
}

// ---------------------------------------------------------------------------
// Per-row combine of 64 partials + fused final reduction (last block)
// ---------------------------------------------------------------------------
__global__ __launch_bounds__(256) void combine_final_kernel(float* __restrict__ out) {
    const int row  = blockIdx.x * 8 + (threadIdx.x >> 5);
    const int lane = threadIdx.x & 31;
    const int t = threadIdx.x;

    float2 p = g_part[(size_t)row * NT + lane * 2];
    float2 q = g_part[(size_t)row * NT + lane * 2 + 1];
    p = lse_combine(p, q);
    float m = p.x, s = p.y;
    #pragma unroll
    for (int d = 1; d < 32; d <<= 1) {
        float mo = __shfl_xor_sync(FULLMASK, m, d);
        float so = __shfl_xor_sync(FULLMASK, s, d);
        float mm = fmaxf(m, mo);
        s = s * __expf(m - mm) + so * __expf(mo - mm);
        m = mm;
    }
    if (lane == 0) g_rowval[row] = m + logf(s) - g_pos[row];

    __shared__ bool amLast;
    __threadfence();
    if (t == 0) {
        int c = atomicAdd(&g_done, 1);
        amLast = (c == (int)gridDim.x - 1);
    }
    __syncthreads();
    if (amLast) {
        float sum = 0.0f;
        #pragma unroll
        for (int k = 0; k < 32; k++) sum += g_rowval[k * 256 + t];
        __shared__ float sm[256];
        sm[t] = sum;
        __syncthreads();
        #pragma unroll
        for (int st = 128; st > 0; st >>= 1) {
            if (t < st) sm[t] += sm[t + st];
            __syncthreads();
        }
        if (t == 0) {
            out[0] = sm[0] / (float)NN;
            g_done = 0;   // reset for next graph replay
        }
    }
}

// ---------------------------------------------------------------------------
extern "C" void kernel_launch(void* const* d_in, const int* in_sizes, int n_in,
                              void* d_out, int out_size) {
    const float* hi = (const float*)d_in[0];
    const float* hj = (const float*)d_in[1];
    float* out = (float*)d_out;

    cudaFuncSetAttribute(gemm_fused_kernel,
                         cudaFuncAttributeMaxDynamicSharedMemorySize, SMEM_BYTES);

    int dev = 0, nsm = 148, occ = 2;
    cudaGetDevice(&dev);
    cudaDeviceGetAttribute(&nsm, cudaDevAttrMultiProcessorCount, dev);
    cudaOccupancyMaxActiveBlocksPerMultiprocessor(
        &occ, gemm_fused_kernel, 256, SMEM_BYTES);
    if (occ < 1) occ = 1;
    int grid = nsm * occ;                 // exactly one resident wave
    if (grid > NTILES) grid = NTILES;

    gemm_fused_kernel<<<grid, 256, SMEM_BYTES>>>(
        (const float4*)hi, (const float4*)hj);
    combine_final_kernel<<<NN / 8, 256>>>(out);
}